// round 9
// baseline (speedup 1.0000x reference)
#include <cuda_runtime.h>
#include <math_constants.h>

#define BATCH 512
#define DIM   256
#define HID   512
#define NC    32      // NUM_COEFF
#define NTAIL 30      // NUM_COEFF - 2
#define NP    64      // Chebyshev points
#define TEV   16
#define MAXIT 10
#define TOLF  0.01f

#define MROWS (BATCH*NP)          // 32768
#define CROWS (BATCH*NC)          // 16384 coefficient-rows
#define BSZ   (BATCH*DIM*NTAIL)   // 3,932,160
#define TRAJ_N (TEV*BATCH*DIM)    // 2,097,152
#define DELTA_OFF (TEV + TRAJ_N)  // 2,097,168
#define B_OFF (DELTA_OFF + 1)     // 2,097,169

// ---------------- scratch (device globals; no allocation allowed) ----------
__device__ float g_B[2][BSZ];                 // Picard coefficient ping-pong
__device__ float g_BT [CROWS*DIM];            // B_fullT [(b,n), d]
__device__ float g_BW [CROWS*HID];            // BW      [(b,n), h]
__device__ float g_hact[(long)MROWS*HID];     // tanh act [(b,p), h]
__device__ float g_HP [CROWS*HID];            // HP      [(b,n), h]
__device__ float g_B1 [CROWS*DIM];            // B1      [(b,n), d]
__device__ float g_yf2[BATCH*DIM*2];
__device__ float g_h0[BATCH*HID];
__device__ float g_fi[BATCH*DIM];
__device__ float g_bsum[BATCH];

// small fp32 operators
__device__ float g_Phi[NC*NP];
__device__ float g_tcheb[NP];
__device__ float g_PD2[NTAIL*2];
__device__ float g_inv0[4];
__device__ float g_PhibTQ[NP*NTAIL];
__device__ float g_M2[2*NTAIL];
__device__ float g_Svec[NTAIL];
__device__ float g_PhiOut[NC*TEV];
__device__ float g_delta;
__device__ int   g_done;

// double precompute workspace
__device__ double gd_tcheb[NP];
__device__ double gd_Dt[NP];
__device__ double gd_Phi[NC*NP];
__device__ double gd_DPhi[NC*NP];
__device__ double gd_C[2*NP];
__device__ double gd_Phib[NTAIL*NP];
__device__ double gd_G[NTAIL*60];       // augmented [G | I]
__device__ double gd_PhibTQ[NP*NTAIL];

#define DPI 3.14159265358979323846

// ---------------- f32x2 helpers (per-lane IEEE fma.rn) ----------------------
__device__ __forceinline__ unsigned long long pk2(float lo, float hi) {
    unsigned long long r;
    asm("mov.b64 %0, {%1, %2};" : "=l"(r) : "f"(lo), "f"(hi));
    return r;
}
__device__ __forceinline__ void upk2(unsigned long long v, float& lo, float& hi) {
    asm("mov.b64 {%0, %1}, %2;" : "=f"(lo), "=f"(hi) : "l"(v));
}
__device__ __forceinline__ unsigned long long fma2(unsigned long long a,
                                                   unsigned long long b,
                                                   unsigned long long c) {
    unsigned long long d;
    asm("fma.rn.f32x2 %0, %1, %2, %3;" : "=l"(d) : "l"(a), "l"(b), "l"(c));
    return d;
}

// ---------------- precompute spectral operators (1 block) ------------------
__global__ void k_precompute(const float* __restrict__ t_eval, int tn) {
    int tid = threadIdx.x;
    double t0 = (double)t_eval[0];
    double t1 = (double)t_eval[tn-1];
    double dtt = t1 - t0;
    double sg = (dtt > 0.0) ? 1.0 : ((dtt < 0.0) ? -1.0 : 0.0);
    double s = 2.0 / dtt;

    if (tid < NP) {
        double tc = -sg * cos(DPI * (double)tid / (double)NP);
        gd_tcheb[tid] = tc;
        g_tcheb[tid] = (float)tc;
        double Tm2 = 1.0, Tm1 = tc;
        gd_Phi[0*NP+tid] = 1.0;
        gd_Phi[1*NP+tid] = tc;
        #pragma unroll
        for (int n = 2; n < NC; n++) {
            double Tn = 2.0*tc*Tm1 - Tm2;
            gd_Phi[n*NP+tid] = Tn; Tm2 = Tm1; Tm1 = Tn;
        }
        double Um1 = 1.0, U = 2.0*tc;
        gd_DPhi[0*NP+tid] = 0.0;
        gd_DPhi[1*NP+tid] = s * 1.0 * Um1;
        gd_DPhi[2*NP+tid] = s * 2.0 * U;
        #pragma unroll
        for (int k = 3; k < NC; k++) {
            double Un = 2.0*tc*U - Um1;
            Um1 = U; U = Un;
            gd_DPhi[k*NP+tid] = s * (double)k * U;
        }
    }
    __syncthreads();
    if (tid < NP)
        gd_Dt[tid] = (tid < NP-1) ? (gd_tcheb[tid+1] - gd_tcheb[tid])
                                  : (1.0 - gd_tcheb[NP-1]);

    __shared__ double sinv0[4];
    if (tid == 0) {
        double a = gd_Phi[0], b = gd_DPhi[0];
        double c = gd_Phi[1*NP], d = gd_DPhi[1*NP];
        double det = a*d - b*c;
        sinv0[0] =  d/det; sinv0[1] = -b/det;
        sinv0[2] = -c/det; sinv0[3] =  a/det;
        g_inv0[0]=(float)sinv0[0]; g_inv0[1]=(float)sinv0[1];
        g_inv0[2]=(float)sinv0[2]; g_inv0[3]=(float)sinv0[3];
        g_done = 0;
        g_delta = CUDART_INF_F;
    }
    __syncthreads();
    if (tid < 2*NP) {
        int k = tid / NP, p = tid % NP;
        gd_C[k*NP+p] = sinv0[k*2+0]*gd_DPhi[0*NP+p] + sinv0[k*2+1]*gd_DPhi[1*NP+p];
    }
    if (tid < NTAIL) {
        g_PD2[tid*2+0] = (float)gd_Phi [(tid+2)*NP + 0];
        g_PD2[tid*2+1] = (float)gd_DPhi[(tid+2)*NP + 0];
    }
    __syncthreads();
    for (int idx = tid; idx < NTAIL*NP; idx += blockDim.x) {
        int j = idx / NP, p = idx % NP;
        double pd0 = gd_Phi [(j+2)*NP + 0];
        double pd1 = gd_DPhi[(j+2)*NP + 0];
        gd_Phib[idx] = gd_DPhi[(j+2)*NP + p] - pd0*gd_C[0*NP+p] - pd1*gd_C[1*NP+p];
    }
    __syncthreads();
    for (int idx = tid; idx < NTAIL*NTAIL; idx += blockDim.x) {
        int i = idx / NTAIL, j = idx % NTAIL;
        double acc = 0.0;
        for (int p = 0; p < NP; p++)
            acc += gd_Phib[i*NP+p] * gd_Dt[p] * gd_Phib[j*NP+p];
        gd_G[i*60 + j] = acc;
        gd_G[i*60 + 30 + j] = (i == j) ? 1.0 : 0.0;
    }
    __syncthreads();
    __shared__ double fac[NTAIL];
    __shared__ double piv;
    for (int k = 0; k < NTAIL; k++) {
        if (tid == 0) piv = 1.0 / gd_G[k*60 + k];
        __syncthreads();
        for (int j = tid; j < 60; j += blockDim.x) gd_G[k*60 + j] *= piv;
        __syncthreads();
        if (tid < NTAIL && tid != k) fac[tid] = gd_G[tid*60 + k];
        __syncthreads();
        for (int idx = tid; idx < NTAIL*60; idx += blockDim.x) {
            int i = idx / 60, j = idx % 60;
            if (i != k) gd_G[idx] -= fac[i] * gd_G[k*60 + j];
        }
        __syncthreads();
    }
    for (int idx = tid; idx < NP*NTAIL; idx += blockDim.x) {
        int p = idx / NTAIL, n = idx % NTAIL;
        double acc = 0.0;
        for (int j = 0; j < NTAIL; j++)
            acc += gd_Phib[j*NP+p] * gd_G[j*60 + 30 + n];
        double v = gd_Dt[p] * acc;
        gd_PhibTQ[idx] = v;
        g_PhibTQ[idx] = (float)v;
    }
    __syncthreads();
    if (tid < 2*NTAIL) {
        int k = tid / NTAIL, n = tid % NTAIL;
        double acc = 0.0;
        for (int p = 0; p < NP; p++)
            acc += gd_C[k*NP+p] * gd_PhibTQ[p*NTAIL + n];
        g_M2[k*NTAIL+n] = (float)acc;
    }
    if (tid < NTAIL) {
        double acc = 0.0;
        for (int p = 0; p < NP; p++) acc += gd_PhibTQ[p*NTAIL + tid];
        g_Svec[tid] = (float)acc;
    }
    for (int idx = tid; idx < NC*NP; idx += blockDim.x)
        g_Phi[idx] = (float)gd_Phi[idx];
    if (tid < TEV) {
        double tt = -1.0 + 2.0*((double)t_eval[tid] - t0)/dtt;
        double Tm2 = 1.0, Tm1 = tt;
        g_PhiOut[0*TEV+tid] = 1.0f;
        g_PhiOut[1*TEV+tid] = (float)tt;
        #pragma unroll
        for (int n = 2; n < NC; n++) {
            double Tn = 2.0*tt*Tm1 - Tm2;
            g_PhiOut[n*TEV+tid] = (float)Tn; Tm2 = Tm1; Tm1 = Tn;
        }
    }
}

// ---------------- generic copy ---------------------------------------------
__global__ void k_copy(const float* __restrict__ src, float* __restrict__ dst, int n) {
    int i = blockIdx.x * blockDim.x + threadIdx.x;
    int stride = gridDim.x * blockDim.x;
    for (; i < n; i += stride) dst[i] = src[i];
}

__global__ void k_copy_if_done(int par) {
    if (!g_done) return;
    const float* src = g_B[par];
    float* dst = g_B[par ^ 1];
    int i = blockIdx.x * blockDim.x + threadIdx.x;
    int stride = gridDim.x * blockDim.x;
    for (; i < BSZ; i += stride) dst[i] = src[i];
}

__global__ void k_yf2(const float* __restrict__ y_init) {
    int i = blockIdx.x * blockDim.x + threadIdx.x;
    if (i < BATCH*DIM) {
        g_yf2[2*i]   = y_init[i];
        g_yf2[2*i+1] = g_fi[i];
    }
}

// ---------------- SGEMM 128x128, K-chunk 16, f32x2 accumulators -------------
// EPI 0: C = tanhf(acc + bias + t)   EPI 1: C = acc + bias   EPI 2: C = acc
// TMODE 0: t = g_tcheb[row & 63]; TMODE 1: t = tvec[0]
template<int EPI, int TMODE, bool CHECK>
__launch_bounds__(256, 2)
__global__ void sgemm(const float* __restrict__ A, const float* __restrict__ B,
                      float* __restrict__ C, const float* __restrict__ bias,
                      const float* __restrict__ tvec, int M, int N, int K) {
    if (CHECK && g_done) return;
    __shared__ __align__(16) float As[2][16][132];   // [k][row], padded
    __shared__ __align__(16) float Bs[2][16][128];   // [k][col]
    const int tid = threadIdx.x;
    const int bm = blockIdx.y * 128, bn = blockIdx.x * 128;
    const int tx = (tid & 15) * 8, ty = (tid >> 4) * 8;
    const int NCH = K >> 4;

    unsigned long long acc2[8][4];
    #pragma unroll
    for (int i = 0; i < 8; i++)
        #pragma unroll
        for (int jp = 0; jp < 4; jp++) acc2[i][jp] = 0ull;

    float4 ra[2], rb[2];
    auto gload = [&](int c) {
        int k0 = c << 4;
        #pragma unroll
        for (int i = 0; i < 2; i++) {
            int idx = (i << 8) + tid;
            ra[i] = *(const float4*)(A + (long)(bm + (idx >> 2)) * K + k0 + ((idx & 3) << 2));
            rb[i] = *(const float4*)(B + (long)(k0 + (idx >> 5)) * N + bn + ((idx & 31) << 2));
        }
    };
    auto sstore = [&](int s) {
        #pragma unroll
        for (int i = 0; i < 2; i++) {
            int idx = (i << 8) + tid;
            int row = idx >> 2, c4 = (idx & 3) << 2;
            As[s][c4+0][row] = ra[i].x;
            As[s][c4+1][row] = ra[i].y;
            As[s][c4+2][row] = ra[i].z;
            As[s][c4+3][row] = ra[i].w;
            *(float4*)&Bs[s][idx >> 5][(idx & 31) << 2] = rb[i];
        }
    };

    gload(0);
    sstore(0);
    if (NCH > 1) gload(1);
    __syncthreads();

    for (int c = 0; c < NCH; c++) {
        int s = c & 1;
        if (c + 1 < NCH) sstore(s ^ 1);
        if (c + 2 < NCH) gload(c + 2);
        #pragma unroll
        for (int k = 0; k < 16; k++) {
            float4 a0 = *(const float4*)&As[s][k][ty];
            float4 a1 = *(const float4*)&As[s][k][ty+4];
            ulonglong2 bb0 = *(const ulonglong2*)&Bs[s][k][tx];
            ulonglong2 bb1 = *(const ulonglong2*)&Bs[s][k][tx+4];
            unsigned long long b2v[4] = {bb0.x, bb0.y, bb1.x, bb1.y};
            float ar[8] = {a0.x,a0.y,a0.z,a0.w,a1.x,a1.y,a1.z,a1.w};
            #pragma unroll
            for (int i = 0; i < 8; i++) {
                unsigned long long ad = pk2(ar[i], ar[i]);
                #pragma unroll
                for (int jp = 0; jp < 4; jp++)
                    acc2[i][jp] = fma2(ad, b2v[jp], acc2[i][jp]);
            }
        }
        __syncthreads();
    }

    float bv[8];
    if (EPI != 2) {
        *(float4*)&bv[0] = *(const float4*)&bias[bn + tx];
        *(float4*)&bv[4] = *(const float4*)&bias[bn + tx + 4];
    }
    float tv1 = 0.0f;
    if (EPI == 0 && TMODE == 1) tv1 = tvec[0];
    #pragma unroll
    for (int i = 0; i < 8; i++) {
        int row = bm + ty + i;
        float a[8];
        #pragma unroll
        for (int jp = 0; jp < 4; jp++) upk2(acc2[i][jp], a[2*jp], a[2*jp+1]);
        float v[8];
        if (EPI == 0) {
            float tval = (TMODE == 0) ? g_tcheb[row & 63] : tv1;
            #pragma unroll
            for (int j = 0; j < 8; j++) v[j] = tanhf(a[j] + bv[j] + tval);
        } else if (EPI == 1) {
            #pragma unroll
            for (int j = 0; j < 8; j++) v[j] = a[j] + bv[j];
        } else {
            #pragma unroll
            for (int j = 0; j < 8; j++) v[j] = a[j];
        }
        *(float4*)&C[(long)row*N + bn + tx]     = *(float4*)&v[0];
        *(float4*)&C[(long)row*N + bn + tx + 4] = *(float4*)&v[4];
    }
}

// ---------------- coefficients: B_fullT[(b,n), d] ---------------------------
__global__ void k_coef(int par) {
    if (g_done) return;
    int b = blockIdx.x, d = threadIdx.x;
    const float* Brow = g_B[par] + (long)(b*DIM + d) * NTAIL;
    float r0 = g_yf2[(b*DIM + d)*2 + 0];
    float r1 = g_yf2[(b*DIM + d)*2 + 1];
    float c[NC];
    #pragma unroll
    for (int j = 0; j < NTAIL; j++) {
        float bj = Brow[j];
        c[j+2] = bj;
        r0 -= bj * g_PD2[j*2+0];
        r1 -= bj * g_PD2[j*2+1];
    }
    c[0] = r0 * g_inv0[0] + r1 * g_inv0[2];
    c[1] = r0 * g_inv0[1] + r1 * g_inv0[3];
    #pragma unroll
    for (int n = 0; n < NC; n++)
        g_BT[(long)(b*NC + n)*DIM + d] = c[n];
}

// ---------------- expand: h = tanh(Phi^T . BW + b1 + t) ---------------------
__global__ void k_expand(const float* __restrict__ b1) {
    if (g_done) return;
    __shared__ float sPhi[NC][NP];
    int tid = threadIdx.x, b = blockIdx.x;
    for (int i = tid; i < NC*NP; i += blockDim.x)
        ((float*)sPhi)[i] = g_Phi[i];
    __syncthreads();
    #pragma unroll
    for (int half = 0; half < 2; half++) {
        int hh = tid + half*256;
        float w[NC];
        #pragma unroll
        for (int n = 0; n < NC; n++)
            w[n] = g_BW[(long)(b*NC + n)*HID + hh];
        float bb = b1[hh];
        for (int p = 0; p < NP; p++) {
            float z = 0.0f;
            #pragma unroll
            for (int n = 0; n < NC; n++) z += w[n] * sPhi[n][p];
            g_hact[(long)(b*NP + p)*HID + hh] = tanhf(z + bb + g_tcheb[p]);
        }
    }
}

// ---------------- HP[(b,n),h] = sum_p h[(b,p),h] PhibTQ[p,n] ----------------
__global__ void k_hp() {
    if (g_done) return;
    __shared__ float sP[NP][NTAIL];
    int tid = threadIdx.x, b = blockIdx.x;
    for (int i = tid; i < NP*NTAIL; i += blockDim.x) ((float*)sP)[i] = g_PhibTQ[i];
    __syncthreads();
    #pragma unroll
    for (int half = 0; half < 2; half++) {
        int hh = tid + half*256;
        float acc[NTAIL];
        #pragma unroll
        for (int n = 0; n < NTAIL; n++) acc[n] = 0.0f;
        for (int p = 0; p < NP; p++) {
            float v = g_hact[(long)(b*NP + p)*HID + hh];
            #pragma unroll
            for (int n = 0; n < NTAIL; n++) acc[n] += v * sP[p][n];
        }
        #pragma unroll
        for (int n = 0; n < NTAIL; n++)
            g_HP[(long)(b*NC + n)*HID + hh] = acc[n];
    }
}

// ---------------- B_new from B1 + bias/M2 terms, delta partials -------------
__global__ void k_bnew(int par, const float* __restrict__ b2) {
    if (g_done) return;
    __shared__ float sM2[2][NTAIL];
    __shared__ float sS[NTAIL];
    int tid = threadIdx.x, b = blockIdx.x;
    if (tid < 2*NTAIL) ((float*)sM2)[tid] = g_M2[tid];
    if (tid < NTAIL) sS[tid] = g_Svec[tid];
    __syncthreads();
    int d = tid;
    float y0 = g_yf2[(b*DIM + d)*2 + 0];
    float y1 = g_yf2[(b*DIM + d)*2 + 1];
    float b2d = b2[d];
    const float* Bp = g_B[par] + (long)(b*DIM + d) * NTAIL;
    float* Bn = g_B[par ^ 1] + (long)(b*DIM + d) * NTAIL;
    float ss = 0.0f;
    #pragma unroll
    for (int n = 0; n < NTAIL; n++) {
        float val = g_B1[(long)(b*NC + n)*DIM + d] + b2d * sS[n]
                  - y0 * sM2[0][n] - y1 * sM2[1][n];
        Bn[n] = val;
        float df = val - Bp[n];
        ss += df * df;
    }
    #pragma unroll
    for (int o = 16; o > 0; o >>= 1) ss += __shfl_down_sync(0xffffffffu, ss, o);
    __shared__ float wsum[8];
    if ((tid & 31) == 0) wsum[tid >> 5] = ss;
    __syncthreads();
    if (tid == 0) {
        float t = 0.0f;
        #pragma unroll
        for (int w = 0; w < 8; w++) t += wsum[w];
        g_bsum[b] = t;
    }
}

__global__ void k_finalize() {
    int tid = threadIdx.x;  // 256 threads
    __shared__ float sh[256];
    if (g_done) return;
    float s = g_bsum[tid] + g_bsum[tid + 256];
    sh[tid] = s;
    __syncthreads();
    for (int o = 128; o > 0; o >>= 1) {
        if (tid < o) sh[tid] += sh[tid + o];
        __syncthreads();
    }
    if (tid == 0) {
        float d = sqrtf(sh[0]);
        g_delta = d;
        if (d < TOLF) g_done = 1;
    }
}

// ---------------- final trajectory ------------------------------------------
__global__ void k_traj(float* __restrict__ out_traj) {
    __shared__ float sPO[NC*TEV];
    int tid = threadIdx.x, b = blockIdx.x;
    for (int i = tid; i < NC*TEV; i += blockDim.x) sPO[i] = g_PhiOut[i];
    __syncthreads();
    int d = tid;
    const float* Brow = g_B[0] + (long)(b*DIM + d) * NTAIL;
    float r0 = g_yf2[(b*DIM + d)*2 + 0];
    float r1 = g_yf2[(b*DIM + d)*2 + 1];
    float c[NC];
    #pragma unroll
    for (int j = 0; j < NTAIL; j++) {
        float bj = Brow[j];
        c[j+2] = bj;
        r0 -= bj * g_PD2[j*2+0];
        r1 -= bj * g_PD2[j*2+1];
    }
    c[0] = r0 * g_inv0[0] + r1 * g_inv0[2];
    c[1] = r0 * g_inv0[1] + r1 * g_inv0[3];
    #pragma unroll
    for (int t = 0; t < TEV; t++) {
        float acc = 0.0f;
        #pragma unroll
        for (int n = 0; n < NC; n++) acc += c[n] * sPO[n*TEV + t];
        out_traj[((long)t*BATCH + b)*DIM + d] = acc;
    }
}

__global__ void k_misc(const float* __restrict__ t_eval, float* __restrict__ out, int tn) {
    int tid = threadIdx.x;
    if (tid < tn) out[tid] = t_eval[tid];
    if (tid == 31) out[DELTA_OFF] = g_delta;
}

// ---------------- launch ----------------------------------------------------
extern "C" void kernel_launch(void* const* d_in, const int* in_sizes, int n_in,
                              void* d_out, int out_size) {
    const float* y_init = (const float*)d_in[0];
    const float* t_eval = (const float*)d_in[1];
    const float* B_init = (const float*)d_in[2];
    const float* W1 = (const float*)d_in[3];
    const float* b1 = (const float*)d_in[4];
    const float* W2 = (const float*)d_in[5];
    const float* b2 = (const float*)d_in[6];
    float* out = (float*)d_out;
    int tn = in_sizes[1];

    float *pB0, *pBT, *pBW, *pHP, *pB1, *ph0, *pfi;
    cudaGetSymbolAddress((void**)&pB0, g_B);
    cudaGetSymbolAddress((void**)&pBT, g_BT);
    cudaGetSymbolAddress((void**)&pBW, g_BW);
    cudaGetSymbolAddress((void**)&pHP, g_HP);
    cudaGetSymbolAddress((void**)&pB1, g_B1);
    cudaGetSymbolAddress((void**)&ph0, g_h0);
    cudaGetSymbolAddress((void**)&pfi, g_fi);

    k_precompute<<<1, 256>>>(t_eval, tn);
    k_copy<<<2048, 256>>>(B_init, pB0, BSZ);

    // f_init = vf_point(t0, y_init)
    sgemm<0, 1, false><<<dim3(HID/128, BATCH/128), 256>>>(
        y_init, W1, ph0, b1, t_eval, BATCH, HID, DIM);
    sgemm<1, 0, false><<<dim3(DIM/128, BATCH/128), 256>>>(
        ph0, W2, pfi, b2, t_eval, BATCH, DIM, HID);
    k_yf2<<<(BATCH*DIM + 255)/256, 256>>>(y_init);

    for (int it = 0; it < MAXIT; it++) {
        int par = it & 1;
        k_coef<<<BATCH, 256>>>(par);
        sgemm<2, 0, true><<<dim3(HID/128, CROWS/128), 256>>>(
            pBT, W1, pBW, b1, t_eval, CROWS, HID, DIM);
        k_expand<<<BATCH, 256>>>(b1);
        k_hp<<<BATCH, 256>>>();
        sgemm<2, 0, true><<<dim3(DIM/128, CROWS/128), 256>>>(
            pHP, W2, pB1, b2, t_eval, CROWS, DIM, HID);
        k_bnew<<<BATCH, 256>>>(par, b2);
        k_copy_if_done<<<2048, 256>>>(par);
        k_finalize<<<1, 256>>>();
    }

    // final B lives in g_B[0] after 10 iterations
    k_traj<<<BATCH, 256>>>(out + TEV);
    k_misc<<<1, 32>>>(t_eval, out, tn);
    k_copy<<<2048, 256>>>(pB0, out + B_OFF, BSZ);
}

// round 11
// speedup vs baseline: 1.7064x; 1.7064x over previous
#include <cuda_runtime.h>
#include <math_constants.h>

#define BATCH 512
#define DIM   256
#define HID   512
#define NC    32      // NUM_COEFF
#define NTAIL 30      // NUM_COEFF - 2
#define NP    64      // Chebyshev points
#define TEV   16
#define MAXIT 10
#define TOLF  0.01f

#define MROWS (BATCH*NP)          // 32768
#define CROWS (BATCH*NC)          // 16384 coefficient-rows
#define BSZ   (BATCH*DIM*NTAIL)   // 3,932,160
#define TRAJ_N (TEV*BATCH*DIM)    // 2,097,152
#define DELTA_OFF (TEV + TRAJ_N)  // 2,097,168
#define B_OFF (DELTA_OFF + 1)     // 2,097,169

// ---------------- scratch (device globals; no allocation allowed) ----------
__device__ float g_B[2][BSZ];                 // Picard coefficient ping-pong
__device__ float g_BT [CROWS*DIM];            // B_fullT [(b,n), d]
__device__ float g_BW [CROWS*HID];            // BW      [(b,n), h]
__device__ float g_HP [CROWS*HID];            // HP      [(b,n), h]
__device__ float g_B1 [CROWS*DIM];            // B1      [(b,n), d]
__device__ float g_yf2[BATCH*DIM*2];
__device__ float g_h0[BATCH*HID];
__device__ float g_fi[BATCH*DIM];
__device__ float g_bsum[BATCH];

// small fp32 operators
__device__ float g_Phi[NC*NP];
__device__ float g_tcheb[NP];
__device__ float g_PD2[NTAIL*2];
__device__ float g_inv0[4];
__device__ float g_PhibTQ[NP*NTAIL];
__device__ float g_M2[2*NTAIL];
__device__ float g_Svec[NTAIL];
__device__ float g_PhiOut[NC*TEV];
__device__ float g_delta;
__device__ int   g_done;

// double precompute workspace
__device__ double gd_tcheb[NP];
__device__ double gd_Dt[NP];
__device__ double gd_Phi[NC*NP];
__device__ double gd_DPhi[NC*NP];
__device__ double gd_C[2*NP];
__device__ double gd_Phib[NTAIL*NP];
__device__ double gd_G[NTAIL*60];       // augmented [G | I]
__device__ double gd_PhibTQ[NP*NTAIL];

#define DPI 3.14159265358979323846

// ---------------- f32x2 helpers (per-lane IEEE fma.rn) ----------------------
__device__ __forceinline__ unsigned long long pk2(float lo, float hi) {
    unsigned long long r;
    asm("mov.b64 %0, {%1, %2};" : "=l"(r) : "f"(lo), "f"(hi));
    return r;
}
__device__ __forceinline__ void upk2(unsigned long long v, float& lo, float& hi) {
    asm("mov.b64 {%0, %1}, %2;" : "=f"(lo), "=f"(hi) : "l"(v));
}
__device__ __forceinline__ unsigned long long fma2(unsigned long long a,
                                                   unsigned long long b,
                                                   unsigned long long c) {
    unsigned long long d;
    asm("fma.rn.f32x2 %0, %1, %2, %3;" : "=l"(d) : "l"(a), "l"(b), "l"(c));
    return d;
}

// ---------------- precompute spectral operators (1 block) ------------------
__global__ void k_precompute(const float* __restrict__ t_eval, int tn) {
    int tid = threadIdx.x;
    double t0 = (double)t_eval[0];
    double t1 = (double)t_eval[tn-1];
    double dtt = t1 - t0;
    double sg = (dtt > 0.0) ? 1.0 : ((dtt < 0.0) ? -1.0 : 0.0);
    double s = 2.0 / dtt;

    if (tid < NP) {
        double tc = -sg * cos(DPI * (double)tid / (double)NP);
        gd_tcheb[tid] = tc;
        g_tcheb[tid] = (float)tc;
        double Tm2 = 1.0, Tm1 = tc;
        gd_Phi[0*NP+tid] = 1.0;
        gd_Phi[1*NP+tid] = tc;
        #pragma unroll
        for (int n = 2; n < NC; n++) {
            double Tn = 2.0*tc*Tm1 - Tm2;
            gd_Phi[n*NP+tid] = Tn; Tm2 = Tm1; Tm1 = Tn;
        }
        double Um1 = 1.0, U = 2.0*tc;
        gd_DPhi[0*NP+tid] = 0.0;
        gd_DPhi[1*NP+tid] = s * 1.0 * Um1;
        gd_DPhi[2*NP+tid] = s * 2.0 * U;
        #pragma unroll
        for (int k = 3; k < NC; k++) {
            double Un = 2.0*tc*U - Um1;
            Um1 = U; U = Un;
            gd_DPhi[k*NP+tid] = s * (double)k * U;
        }
    }
    __syncthreads();
    if (tid < NP)
        gd_Dt[tid] = (tid < NP-1) ? (gd_tcheb[tid+1] - gd_tcheb[tid])
                                  : (1.0 - gd_tcheb[NP-1]);

    __shared__ double sinv0[4];
    if (tid == 0) {
        double a = gd_Phi[0], b = gd_DPhi[0];
        double c = gd_Phi[1*NP], d = gd_DPhi[1*NP];
        double det = a*d - b*c;
        sinv0[0] =  d/det; sinv0[1] = -b/det;
        sinv0[2] = -c/det; sinv0[3] =  a/det;
        g_inv0[0]=(float)sinv0[0]; g_inv0[1]=(float)sinv0[1];
        g_inv0[2]=(float)sinv0[2]; g_inv0[3]=(float)sinv0[3];
        g_done = 0;
        g_delta = CUDART_INF_F;
    }
    __syncthreads();
    if (tid < 2*NP) {
        int k = tid / NP, p = tid % NP;
        gd_C[k*NP+p] = sinv0[k*2+0]*gd_DPhi[0*NP+p] + sinv0[k*2+1]*gd_DPhi[1*NP+p];
    }
    if (tid < NTAIL) {
        g_PD2[tid*2+0] = (float)gd_Phi [(tid+2)*NP + 0];
        g_PD2[tid*2+1] = (float)gd_DPhi[(tid+2)*NP + 0];
    }
    __syncthreads();
    for (int idx = tid; idx < NTAIL*NP; idx += blockDim.x) {
        int j = idx / NP, p = idx % NP;
        double pd0 = gd_Phi [(j+2)*NP + 0];
        double pd1 = gd_DPhi[(j+2)*NP + 0];
        gd_Phib[idx] = gd_DPhi[(j+2)*NP + p] - pd0*gd_C[0*NP+p] - pd1*gd_C[1*NP+p];
    }
    __syncthreads();
    for (int idx = tid; idx < NTAIL*NTAIL; idx += blockDim.x) {
        int i = idx / NTAIL, j = idx % NTAIL;
        double acc = 0.0;
        for (int p = 0; p < NP; p++)
            acc += gd_Phib[i*NP+p] * gd_Dt[p] * gd_Phib[j*NP+p];
        gd_G[i*60 + j] = acc;
        gd_G[i*60 + 30 + j] = (i == j) ? 1.0 : 0.0;
    }
    __syncthreads();
    __shared__ double fac[NTAIL];
    __shared__ double piv;
    for (int k = 0; k < NTAIL; k++) {
        if (tid == 0) piv = 1.0 / gd_G[k*60 + k];
        __syncthreads();
        for (int j = tid; j < 60; j += blockDim.x) gd_G[k*60 + j] *= piv;
        __syncthreads();
        if (tid < NTAIL && tid != k) fac[tid] = gd_G[tid*60 + k];
        __syncthreads();
        for (int idx = tid; idx < NTAIL*60; idx += blockDim.x) {
            int i = idx / 60, j = idx % 60;
            if (i != k) gd_G[idx] -= fac[i] * gd_G[k*60 + j];
        }
        __syncthreads();
    }
    for (int idx = tid; idx < NP*NTAIL; idx += blockDim.x) {
        int p = idx / NTAIL, n = idx % NTAIL;
        double acc = 0.0;
        for (int j = 0; j < NTAIL; j++)
            acc += gd_Phib[j*NP+p] * gd_G[j*60 + 30 + n];
        double v = gd_Dt[p] * acc;
        gd_PhibTQ[idx] = v;
        g_PhibTQ[idx] = (float)v;
    }
    __syncthreads();
    if (tid < 2*NTAIL) {
        int k = tid / NTAIL, n = tid % NTAIL;
        double acc = 0.0;
        for (int p = 0; p < NP; p++)
            acc += gd_C[k*NP+p] * gd_PhibTQ[p*NTAIL + n];
        g_M2[k*NTAIL+n] = (float)acc;
    }
    if (tid < NTAIL) {
        double acc = 0.0;
        for (int p = 0; p < NP; p++) acc += gd_PhibTQ[p*NTAIL + tid];
        g_Svec[tid] = (float)acc;
    }
    for (int idx = tid; idx < NC*NP; idx += blockDim.x)
        g_Phi[idx] = (float)gd_Phi[idx];
    if (tid < TEV) {
        double tt = -1.0 + 2.0*((double)t_eval[tid] - t0)/dtt;
        double Tm2 = 1.0, Tm1 = tt;
        g_PhiOut[0*TEV+tid] = 1.0f;
        g_PhiOut[1*TEV+tid] = (float)tt;
        #pragma unroll
        for (int n = 2; n < NC; n++) {
            double Tn = 2.0*tt*Tm1 - Tm2;
            g_PhiOut[n*TEV+tid] = (float)Tn; Tm2 = Tm1; Tm1 = Tn;
        }
    }
}

// ---------------- generic copy ---------------------------------------------
__global__ void k_copy(const float* __restrict__ src, float* __restrict__ dst, int n) {
    int i = blockIdx.x * blockDim.x + threadIdx.x;
    int stride = gridDim.x * blockDim.x;
    for (; i < n; i += stride) dst[i] = src[i];
}

__global__ void k_copy_if_done(int par) {
    if (!g_done) return;
    const float* src = g_B[par];
    float* dst = g_B[par ^ 1];
    int i = blockIdx.x * blockDim.x + threadIdx.x;
    int stride = gridDim.x * blockDim.x;
    for (; i < BSZ; i += stride) dst[i] = src[i];
}

__global__ void k_yf2(const float* __restrict__ y_init) {
    int i = blockIdx.x * blockDim.x + threadIdx.x;
    if (i < BATCH*DIM) {
        g_yf2[2*i]   = y_init[i];
        g_yf2[2*i+1] = g_fi[i];
    }
}

// ---------------- SGEMM 128x128, K-chunk 16, f32x2 accumulators -------------
// EPI 0: C = tanhf(acc + bias + t)   EPI 1: C = acc + bias   EPI 2: C = acc
// TMODE 0: t = g_tcheb[row & 63]; TMODE 1: t = tvec[0]
template<int EPI, int TMODE, bool CHECK>
__launch_bounds__(256, 2)
__global__ void sgemm(const float* __restrict__ A, const float* __restrict__ B,
                      float* __restrict__ C, const float* __restrict__ bias,
                      const float* __restrict__ tvec, int M, int N, int K) {
    if (CHECK && g_done) return;
    __shared__ __align__(16) float As[2][16][132];   // [k][row], padded
    __shared__ __align__(16) float Bs[2][16][128];   // [k][col]
    const int tid = threadIdx.x;
    const int bm = blockIdx.y * 128, bn = blockIdx.x * 128;
    const int tx = (tid & 15) * 8, ty = (tid >> 4) * 8;
    const int NCH = K >> 4;

    unsigned long long acc2[8][4];
    #pragma unroll
    for (int i = 0; i < 8; i++)
        #pragma unroll
        for (int jp = 0; jp < 4; jp++) acc2[i][jp] = 0ull;

    float4 ra[2], rb[2];
    auto gload = [&](int c) {
        int k0 = c << 4;
        #pragma unroll
        for (int i = 0; i < 2; i++) {
            int idx = (i << 8) + tid;
            ra[i] = *(const float4*)(A + (long)(bm + (idx >> 2)) * K + k0 + ((idx & 3) << 2));
            rb[i] = *(const float4*)(B + (long)(k0 + (idx >> 5)) * N + bn + ((idx & 31) << 2));
        }
    };
    auto sstore = [&](int s) {
        #pragma unroll
        for (int i = 0; i < 2; i++) {
            int idx = (i << 8) + tid;
            int row = idx >> 2, c4 = (idx & 3) << 2;
            As[s][c4+0][row] = ra[i].x;
            As[s][c4+1][row] = ra[i].y;
            As[s][c4+2][row] = ra[i].z;
            As[s][c4+3][row] = ra[i].w;
            *(float4*)&Bs[s][idx >> 5][(idx & 31) << 2] = rb[i];
        }
    };

    gload(0);
    sstore(0);
    if (NCH > 1) gload(1);
    __syncthreads();

    for (int c = 0; c < NCH; c++) {
        int s = c & 1;
        if (c + 1 < NCH) sstore(s ^ 1);
        if (c + 2 < NCH) gload(c + 2);
        #pragma unroll
        for (int k = 0; k < 16; k++) {
            float4 a0 = *(const float4*)&As[s][k][ty];
            float4 a1 = *(const float4*)&As[s][k][ty+4];
            ulonglong2 bb0 = *(const ulonglong2*)&Bs[s][k][tx];
            ulonglong2 bb1 = *(const ulonglong2*)&Bs[s][k][tx+4];
            unsigned long long b2v[4] = {bb0.x, bb0.y, bb1.x, bb1.y};
            float ar[8] = {a0.x,a0.y,a0.z,a0.w,a1.x,a1.y,a1.z,a1.w};
            #pragma unroll
            for (int i = 0; i < 8; i++) {
                unsigned long long ad = pk2(ar[i], ar[i]);
                #pragma unroll
                for (int jp = 0; jp < 4; jp++)
                    acc2[i][jp] = fma2(ad, b2v[jp], acc2[i][jp]);
            }
        }
        __syncthreads();
    }

    float bv[8];
    if (EPI != 2) {
        *(float4*)&bv[0] = *(const float4*)&bias[bn + tx];
        *(float4*)&bv[4] = *(const float4*)&bias[bn + tx + 4];
    }
    float tv1 = 0.0f;
    if (EPI == 0 && TMODE == 1) tv1 = tvec[0];
    #pragma unroll
    for (int i = 0; i < 8; i++) {
        int row = bm + ty + i;
        float a[8];
        #pragma unroll
        for (int jp = 0; jp < 4; jp++) upk2(acc2[i][jp], a[2*jp], a[2*jp+1]);
        float v[8];
        if (EPI == 0) {
            float tval = (TMODE == 0) ? g_tcheb[row & 63] : tv1;
            #pragma unroll
            for (int j = 0; j < 8; j++) v[j] = tanhf(a[j] + bv[j] + tval);
        } else if (EPI == 1) {
            #pragma unroll
            for (int j = 0; j < 8; j++) v[j] = a[j] + bv[j];
        } else {
            #pragma unroll
            for (int j = 0; j < 8; j++) v[j] = a[j];
        }
        *(float4*)&C[(long)row*N + bn + tx]     = *(float4*)&v[0];
        *(float4*)&C[(long)row*N + bn + tx + 4] = *(float4*)&v[4];
    }
}

// ---------------- coefficients: B_fullT[(b,n), d] ---------------------------
__global__ void k_coef(int par) {
    if (g_done) return;
    int b = blockIdx.x, d = threadIdx.x;
    const float* Brow = g_B[par] + (long)(b*DIM + d) * NTAIL;
    float r0 = g_yf2[(b*DIM + d)*2 + 0];
    float r1 = g_yf2[(b*DIM + d)*2 + 1];
    float c[NC];
    #pragma unroll
    for (int j = 0; j < NTAIL; j++) {
        float bj = Brow[j];
        c[j+2] = bj;
        r0 -= bj * g_PD2[j*2+0];
        r1 -= bj * g_PD2[j*2+1];
    }
    c[0] = r0 * g_inv0[0] + r1 * g_inv0[2];
    c[1] = r0 * g_inv0[1] + r1 * g_inv0[3];
    #pragma unroll
    for (int n = 0; n < NC; n++)
        g_BT[(long)(b*NC + n)*DIM + d] = c[n];
}

// ---------------- fused expand+project: h never touches gmem ----------------
// For (b, hh): z_p = sum_n Phi[n][p]*BW[b,n,hh]; v_p = tanh(z_p + b1 + t_p);
// HP[b,n,hh] = sum_p v_p * PhibTQ[p][n]   (acc order p ascending, exact as R8)
__global__ void k_expandhp(const float* __restrict__ b1) {
    if (g_done) return;
    __shared__ float sPhi[NC][NP];
    __shared__ __align__(8) float sP[NP][32];   // PhibTQ padded to 32 for f32x2 pairs
    int tid = threadIdx.x, b = blockIdx.x, half = blockIdx.y;
    for (int i = tid; i < NC*NP; i += blockDim.x)
        ((float*)sPhi)[i] = g_Phi[i];
    for (int i = tid; i < NP*NTAIL; i += blockDim.x) {
        int p = i / NTAIL, n = i % NTAIL;
        sP[p][n] = g_PhibTQ[i];
    }
    if (tid < 2*NP) sP[tid >> 1][30 + (tid & 1)] = 0.0f;
    __syncthreads();

    int hh = half*256 + tid;
    float w[NC];
    #pragma unroll
    for (int n = 0; n < NC; n++)
        w[n] = g_BW[(long)(b*NC + n)*HID + hh];
    float bb = b1[hh];

    unsigned long long acc2[15];
    #pragma unroll
    for (int j = 0; j < 15; j++) acc2[j] = 0ull;

    for (int p = 0; p < NP; p++) {
        float z = 0.0f;
        #pragma unroll
        for (int n = 0; n < NC; n++) z += w[n] * sPhi[n][p];
        float v = tanhf(z + bb + g_tcheb[p]);
        unsigned long long vd = pk2(v, v);
        const unsigned long long* P2 = (const unsigned long long*)&sP[p][0];
        #pragma unroll
        for (int j = 0; j < 15; j++)
            acc2[j] = fma2(vd, P2[j], acc2[j]);
    }
    #pragma unroll
    for (int j = 0; j < 15; j++) {
        float a0, a1;
        upk2(acc2[j], a0, a1);
        g_HP[(long)(b*NC + 2*j    )*HID + hh] = a0;
        g_HP[(long)(b*NC + 2*j + 1)*HID + hh] = a1;
    }
}

// ---------------- B_new from B1 + bias/M2 terms, delta partials -------------
__global__ void k_bnew(int par, const float* __restrict__ b2) {
    if (g_done) return;
    __shared__ float sM2[2][NTAIL];
    __shared__ float sS[NTAIL];
    int tid = threadIdx.x, b = blockIdx.x;
    if (tid < 2*NTAIL) ((float*)sM2)[tid] = g_M2[tid];
    if (tid < NTAIL) sS[tid] = g_Svec[tid];
    __syncthreads();
    int d = tid;
    float y0 = g_yf2[(b*DIM + d)*2 + 0];
    float y1 = g_yf2[(b*DIM + d)*2 + 1];
    float b2d = b2[d];
    const float* Bp = g_B[par] + (long)(b*DIM + d) * NTAIL;
    float* Bn = g_B[par ^ 1] + (long)(b*DIM + d) * NTAIL;
    float ss = 0.0f;
    #pragma unroll
    for (int n = 0; n < NTAIL; n++) {
        float val = g_B1[(long)(b*NC + n)*DIM + d] + b2d * sS[n]
                  - y0 * sM2[0][n] - y1 * sM2[1][n];
        Bn[n] = val;
        float df = val - Bp[n];
        ss += df * df;
    }
    #pragma unroll
    for (int o = 16; o > 0; o >>= 1) ss += __shfl_down_sync(0xffffffffu, ss, o);
    __shared__ float wsum[8];
    if ((tid & 31) == 0) wsum[tid >> 5] = ss;
    __syncthreads();
    if (tid == 0) {
        float t = 0.0f;
        #pragma unroll
        for (int w = 0; w < 8; w++) t += wsum[w];
        g_bsum[b] = t;
    }
}

__global__ void k_finalize() {
    int tid = threadIdx.x;  // 256 threads
    __shared__ float sh[256];
    if (g_done) return;
    float s = g_bsum[tid] + g_bsum[tid + 256];
    sh[tid] = s;
    __syncthreads();
    for (int o = 128; o > 0; o >>= 1) {
        if (tid < o) sh[tid] += sh[tid + o];
        __syncthreads();
    }
    if (tid == 0) {
        float d = sqrtf(sh[0]);
        g_delta = d;
        if (d < TOLF) g_done = 1;
    }
}

// ---------------- final trajectory ------------------------------------------
__global__ void k_traj(float* __restrict__ out_traj) {
    __shared__ float sPO[NC*TEV];
    int tid = threadIdx.x, b = blockIdx.x;
    for (int i = tid; i < NC*TEV; i += blockDim.x) sPO[i] = g_PhiOut[i];
    __syncthreads();
    int d = tid;
    const float* Brow = g_B[0] + (long)(b*DIM + d) * NTAIL;
    float r0 = g_yf2[(b*DIM + d)*2 + 0];
    float r1 = g_yf2[(b*DIM + d)*2 + 1];
    float c[NC];
    #pragma unroll
    for (int j = 0; j < NTAIL; j++) {
        float bj = Brow[j];
        c[j+2] = bj;
        r0 -= bj * g_PD2[j*2+0];
        r1 -= bj * g_PD2[j*2+1];
    }
    c[0] = r0 * g_inv0[0] + r1 * g_inv0[2];
    c[1] = r0 * g_inv0[1] + r1 * g_inv0[3];
    #pragma unroll
    for (int t = 0; t < TEV; t++) {
        float acc = 0.0f;
        #pragma unroll
        for (int n = 0; n < NC; n++) acc += c[n] * sPO[n*TEV + t];
        out_traj[((long)t*BATCH + b)*DIM + d] = acc;
    }
}

__global__ void k_misc(const float* __restrict__ t_eval, float* __restrict__ out, int tn) {
    int tid = threadIdx.x;
    if (tid < tn) out[tid] = t_eval[tid];
    if (tid == 31) out[DELTA_OFF] = g_delta;
}

// ---------------- launch ----------------------------------------------------
extern "C" void kernel_launch(void* const* d_in, const int* in_sizes, int n_in,
                              void* d_out, int out_size) {
    const float* y_init = (const float*)d_in[0];
    const float* t_eval = (const float*)d_in[1];
    const float* B_init = (const float*)d_in[2];
    const float* W1 = (const float*)d_in[3];
    const float* b1 = (const float*)d_in[4];
    const float* W2 = (const float*)d_in[5];
    const float* b2 = (const float*)d_in[6];
    float* out = (float*)d_out;
    int tn = in_sizes[1];

    float *pB0, *pBT, *pBW, *pHP, *pB1, *ph0, *pfi;
    cudaGetSymbolAddress((void**)&pB0, g_B);
    cudaGetSymbolAddress((void**)&pBT, g_BT);
    cudaGetSymbolAddress((void**)&pBW, g_BW);
    cudaGetSymbolAddress((void**)&pHP, g_HP);
    cudaGetSymbolAddress((void**)&pB1, g_B1);
    cudaGetSymbolAddress((void**)&ph0, g_h0);
    cudaGetSymbolAddress((void**)&pfi, g_fi);

    k_precompute<<<1, 256>>>(t_eval, tn);
    k_copy<<<2048, 256>>>(B_init, pB0, BSZ);

    // f_init = vf_point(t0, y_init)
    sgemm<0, 1, false><<<dim3(HID/128, BATCH/128), 256>>>(
        y_init, W1, ph0, b1, t_eval, BATCH, HID, DIM);
    sgemm<1, 0, false><<<dim3(DIM/128, BATCH/128), 256>>>(
        ph0, W2, pfi, b2, t_eval, BATCH, DIM, HID);
    k_yf2<<<(BATCH*DIM + 255)/256, 256>>>(y_init);

    for (int it = 0; it < MAXIT; it++) {
        int par = it & 1;
        k_coef<<<BATCH, 256>>>(par);
        sgemm<2, 0, true><<<dim3(HID/128, CROWS/128), 256>>>(
            pBT, W1, pBW, b1, t_eval, CROWS, HID, DIM);
        k_expandhp<<<dim3(BATCH, 2), 256>>>(b1);
        sgemm<2, 0, true><<<dim3(DIM/128, CROWS/128), 256>>>(
            pHP, W2, pB1, b2, t_eval, CROWS, DIM, HID);
        k_bnew<<<BATCH, 256>>>(par, b2);
        k_copy_if_done<<<2048, 256>>>(par);
        k_finalize<<<1, 256>>>();
    }

    // final B lives in g_B[0] after 10 iterations
    k_traj<<<BATCH, 256>>>(out + TEV);
    k_misc<<<1, 32>>>(t_eval, out, tn);
    k_copy<<<2048, 256>>>(pB0, out + B_OFF, BSZ);
}

// round 14
// speedup vs baseline: 1.8552x; 1.0872x over previous
#include <cuda_runtime.h>
#include <math_constants.h>

#define BATCH 512
#define DIM   256
#define HID   512
#define NC    32      // NUM_COEFF
#define NTAIL 30      // NUM_COEFF - 2
#define NP    64      // Chebyshev points
#define TEV   16
#define MAXIT 10
#define TOLF  0.01f

#define MROWS (BATCH*NP)          // 32768
#define CROWS (BATCH*NC)          // 16384 coefficient-rows
#define BSZ   (BATCH*DIM*NTAIL)   // 3,932,160
#define TRAJ_N (TEV*BATCH*DIM)    // 2,097,152
#define DELTA_OFF (TEV + TRAJ_N)  // 2,097,168
#define B_OFF (DELTA_OFF + 1)     // 2,097,169

// ---------------- scratch (device globals; no allocation allowed) ----------
__device__ float g_B[2][BSZ];                 // Picard coefficient ping-pong
__device__ float g_BT [CROWS*DIM];            // B_fullT [(b,n), d]
__device__ float g_BW [CROWS*HID];            // BW      [(b,n), h]
__device__ float g_HP [CROWS*HID];            // HP      [(b,n), h]
__device__ float g_B1 [CROWS*DIM];            // B1      [(b,n), d]
__device__ float g_yf2[BATCH*DIM*2];
__device__ float g_h0[BATCH*HID];
__device__ float g_fi[BATCH*DIM];
__device__ float g_bsum[BATCH];

// small fp32 operators
__device__ float g_Phi[NC*NP];
__device__ float g_tcheb[NP];
__device__ float g_PD2[NTAIL*2];
__device__ float g_inv0[4];
__device__ float g_PhibTQ[NP*NTAIL];
__device__ float g_M2[2*NTAIL];
__device__ float g_Svec[NTAIL];
__device__ float g_PhiOut[NC*TEV];
__device__ float g_delta;
__device__ int   g_done;
__device__ int   g_fpar;

// double precompute workspace
__device__ double gd_tcheb[NP];
__device__ double gd_Dt[NP];
__device__ double gd_Phi[NC*NP];
__device__ double gd_DPhi[NC*NP];
__device__ double gd_C[2*NP];
__device__ double gd_Phib[NTAIL*NP];
__device__ double gd_G[NTAIL*60];       // augmented [G | I]
__device__ double gd_PhibTQ[NP*NTAIL];

#define DPI 3.14159265358979323846

// ---------------- f32x2 helpers (per-lane IEEE fma.rn) ----------------------
__device__ __forceinline__ unsigned long long pk2(float lo, float hi) {
    unsigned long long r;
    asm("mov.b64 %0, {%1, %2};" : "=l"(r) : "f"(lo), "f"(hi));
    return r;
}
__device__ __forceinline__ void upk2(unsigned long long v, float& lo, float& hi) {
    asm("mov.b64 {%0, %1}, %2;" : "=f"(lo), "=f"(hi) : "l"(v));
}
__device__ __forceinline__ unsigned long long fma2(unsigned long long a,
                                                   unsigned long long b,
                                                   unsigned long long c) {
    unsigned long long d;
    asm("fma.rn.f32x2 %0, %1, %2, %3;" : "=l"(d) : "l"(a), "l"(b), "l"(c));
    return d;
}

// ---------------- precompute spectral operators (1 block) ------------------
__global__ void k_precompute(const float* __restrict__ t_eval, int tn) {
    int tid = threadIdx.x;
    double t0 = (double)t_eval[0];
    double t1 = (double)t_eval[tn-1];
    double dtt = t1 - t0;
    double sg = (dtt > 0.0) ? 1.0 : ((dtt < 0.0) ? -1.0 : 0.0);
    double s = 2.0 / dtt;

    if (tid < NP) {
        double tc = -sg * cos(DPI * (double)tid / (double)NP);
        gd_tcheb[tid] = tc;
        g_tcheb[tid] = (float)tc;
        double Tm2 = 1.0, Tm1 = tc;
        gd_Phi[0*NP+tid] = 1.0;
        gd_Phi[1*NP+tid] = tc;
        #pragma unroll
        for (int n = 2; n < NC; n++) {
            double Tn = 2.0*tc*Tm1 - Tm2;
            gd_Phi[n*NP+tid] = Tn; Tm2 = Tm1; Tm1 = Tn;
        }
        double Um1 = 1.0, U = 2.0*tc;
        gd_DPhi[0*NP+tid] = 0.0;
        gd_DPhi[1*NP+tid] = s * 1.0 * Um1;
        gd_DPhi[2*NP+tid] = s * 2.0 * U;
        #pragma unroll
        for (int k = 3; k < NC; k++) {
            double Un = 2.0*tc*U - Um1;
            Um1 = U; U = Un;
            gd_DPhi[k*NP+tid] = s * (double)k * U;
        }
    }
    __syncthreads();
    if (tid < NP)
        gd_Dt[tid] = (tid < NP-1) ? (gd_tcheb[tid+1] - gd_tcheb[tid])
                                  : (1.0 - gd_tcheb[NP-1]);

    __shared__ double sinv0[4];
    if (tid == 0) {
        double a = gd_Phi[0], b = gd_DPhi[0];
        double c = gd_Phi[1*NP], d = gd_DPhi[1*NP];
        double det = a*d - b*c;
        sinv0[0] =  d/det; sinv0[1] = -b/det;
        sinv0[2] = -c/det; sinv0[3] =  a/det;
        g_inv0[0]=(float)sinv0[0]; g_inv0[1]=(float)sinv0[1];
        g_inv0[2]=(float)sinv0[2]; g_inv0[3]=(float)sinv0[3];
        g_done = 0;
        g_fpar = 0;
        g_delta = CUDART_INF_F;
    }
    __syncthreads();
    if (tid < 2*NP) {
        int k = tid / NP, p = tid % NP;
        gd_C[k*NP+p] = sinv0[k*2+0]*gd_DPhi[0*NP+p] + sinv0[k*2+1]*gd_DPhi[1*NP+p];
    }
    if (tid < NTAIL) {
        g_PD2[tid*2+0] = (float)gd_Phi [(tid+2)*NP + 0];
        g_PD2[tid*2+1] = (float)gd_DPhi[(tid+2)*NP + 0];
    }
    __syncthreads();
    for (int idx = tid; idx < NTAIL*NP; idx += blockDim.x) {
        int j = idx / NP, p = idx % NP;
        double pd0 = gd_Phi [(j+2)*NP + 0];
        double pd1 = gd_DPhi[(j+2)*NP + 0];
        gd_Phib[idx] = gd_DPhi[(j+2)*NP + p] - pd0*gd_C[0*NP+p] - pd1*gd_C[1*NP+p];
    }
    __syncthreads();
    for (int idx = tid; idx < NTAIL*NTAIL; idx += blockDim.x) {
        int i = idx / NTAIL, j = idx % NTAIL;
        double acc = 0.0;
        for (int p = 0; p < NP; p++)
            acc += gd_Phib[i*NP+p] * gd_Dt[p] * gd_Phib[j*NP+p];
        gd_G[i*60 + j] = acc;
        gd_G[i*60 + 30 + j] = (i == j) ? 1.0 : 0.0;
    }
    __syncthreads();
    __shared__ double fac[NTAIL];
    __shared__ double piv;
    for (int k = 0; k < NTAIL; k++) {
        if (tid == 0) piv = 1.0 / gd_G[k*60 + k];
        __syncthreads();
        for (int j = tid; j < 60; j += blockDim.x) gd_G[k*60 + j] *= piv;
        __syncthreads();
        if (tid < NTAIL && tid != k) fac[tid] = gd_G[tid*60 + k];
        __syncthreads();
        for (int idx = tid; idx < NTAIL*60; idx += blockDim.x) {
            int i = idx / 60, j = idx % 60;
            if (i != k) gd_G[idx] -= fac[i] * gd_G[k*60 + j];
        }
        __syncthreads();
    }
    for (int idx = tid; idx < NP*NTAIL; idx += blockDim.x) {
        int p = idx / NTAIL, n = idx % NTAIL;
        double acc = 0.0;
        for (int j = 0; j < NTAIL; j++)
            acc += gd_Phib[j*NP+p] * gd_G[j*60 + 30 + n];
        double v = gd_Dt[p] * acc;
        gd_PhibTQ[idx] = v;
        g_PhibTQ[idx] = (float)v;
    }
    __syncthreads();
    if (tid < 2*NTAIL) {
        int k = tid / NTAIL, n = tid % NTAIL;
        double acc = 0.0;
        for (int p = 0; p < NP; p++)
            acc += gd_C[k*NP+p] * gd_PhibTQ[p*NTAIL + n];
        g_M2[k*NTAIL+n] = (float)acc;
    }
    if (tid < NTAIL) {
        double acc = 0.0;
        for (int p = 0; p < NP; p++) acc += gd_PhibTQ[p*NTAIL + tid];
        g_Svec[tid] = (float)acc;
    }
    for (int idx = tid; idx < NC*NP; idx += blockDim.x)
        g_Phi[idx] = (float)gd_Phi[idx];
    if (tid < TEV) {
        double tt = -1.0 + 2.0*((double)t_eval[tid] - t0)/dtt;
        double Tm2 = 1.0, Tm1 = tt;
        g_PhiOut[0*TEV+tid] = 1.0f;
        g_PhiOut[1*TEV+tid] = (float)tt;
        #pragma unroll
        for (int n = 2; n < NC; n++) {
            double Tn = 2.0*tt*Tm1 - Tm2;
            g_PhiOut[n*TEV+tid] = (float)Tn; Tm2 = Tm1; Tm1 = Tn;
        }
    }
}

// ---------------- generic copy ---------------------------------------------
__global__ void k_copy(const float* __restrict__ src, float* __restrict__ dst, int n) {
    int i = blockIdx.x * blockDim.x + threadIdx.x;
    int stride = gridDim.x * blockDim.x;
    for (; i < n; i += stride) dst[i] = src[i];
}

// final-B copy: source parity resolved on device
__global__ void k_copyB(float* __restrict__ dst) {
    const float* src = g_B[g_fpar];
    int i = blockIdx.x * blockDim.x + threadIdx.x;
    int stride = gridDim.x * blockDim.x;
    for (; i < BSZ; i += stride) dst[i] = src[i];
}

__global__ void k_yf2(const float* __restrict__ y_init) {
    int i = blockIdx.x * blockDim.x + threadIdx.x;
    if (i < BATCH*DIM) {
        g_yf2[2*i]   = y_init[i];
        g_yf2[2*i+1] = g_fi[i];
    }
}

// ---------------- SGEMM 128x128, K-chunk 16, f32x2 accumulators -------------
// EPI 0: C = tanhf(acc + bias + t)   EPI 1: C = acc + bias   EPI 2: C = acc
// TMODE 0: t = g_tcheb[row & 63]; TMODE 1: t = tvec[0]
template<int EPI, int TMODE, bool CHECK>
__launch_bounds__(256, 2)
__global__ void sgemm(const float* __restrict__ A, const float* __restrict__ B,
                      float* __restrict__ C, const float* __restrict__ bias,
                      const float* __restrict__ tvec, int M, int N, int K) {
    if (CHECK && g_done) return;
    __shared__ __align__(16) float As[2][16][132];   // [k][row], padded
    __shared__ __align__(16) float Bs[2][16][128];   // [k][col]
    const int tid = threadIdx.x;
    const int bm = blockIdx.y * 128, bn = blockIdx.x * 128;
    const int tx = (tid & 15) * 8, ty = (tid >> 4) * 8;
    const int NCH = K >> 4;

    unsigned long long acc2[8][4];
    #pragma unroll
    for (int i = 0; i < 8; i++)
        #pragma unroll
        for (int jp = 0; jp < 4; jp++) acc2[i][jp] = 0ull;

    float4 ra[2], rb[2];
    auto gload = [&](int c) {
        int k0 = c << 4;
        #pragma unroll
        for (int i = 0; i < 2; i++) {
            int idx = (i << 8) + tid;
            ra[i] = *(const float4*)(A + (long)(bm + (idx >> 2)) * K + k0 + ((idx & 3) << 2));
            rb[i] = *(const float4*)(B + (long)(k0 + (idx >> 5)) * N + bn + ((idx & 31) << 2));
        }
    };
    auto sstore = [&](int s) {
        #pragma unroll
        for (int i = 0; i < 2; i++) {
            int idx = (i << 8) + tid;
            int row = idx >> 2, c4 = (idx & 3) << 2;
            As[s][c4+0][row] = ra[i].x;
            As[s][c4+1][row] = ra[i].y;
            As[s][c4+2][row] = ra[i].z;
            As[s][c4+3][row] = ra[i].w;
            *(float4*)&Bs[s][idx >> 5][(idx & 31) << 2] = rb[i];
        }
    };

    gload(0);
    sstore(0);
    if (NCH > 1) gload(1);
    __syncthreads();

    for (int c = 0; c < NCH; c++) {
        int s = c & 1;
        if (c + 1 < NCH) sstore(s ^ 1);
        if (c + 2 < NCH) gload(c + 2);
        #pragma unroll
        for (int k = 0; k < 16; k++) {
            float4 a0 = *(const float4*)&As[s][k][ty];
            float4 a1 = *(const float4*)&As[s][k][ty+4];
            ulonglong2 bb0 = *(const ulonglong2*)&Bs[s][k][tx];
            ulonglong2 bb1 = *(const ulonglong2*)&Bs[s][k][tx+4];
            unsigned long long b2v[4] = {bb0.x, bb0.y, bb1.x, bb1.y};
            float ar[8] = {a0.x,a0.y,a0.z,a0.w,a1.x,a1.y,a1.z,a1.w};
            #pragma unroll
            for (int i = 0; i < 8; i++) {
                unsigned long long ad = pk2(ar[i], ar[i]);
                #pragma unroll
                for (int jp = 0; jp < 4; jp++)
                    acc2[i][jp] = fma2(ad, b2v[jp], acc2[i][jp]);
            }
        }
        __syncthreads();
    }

    float bv[8];
    if (EPI != 2) {
        *(float4*)&bv[0] = *(const float4*)&bias[bn + tx];
        *(float4*)&bv[4] = *(const float4*)&bias[bn + tx + 4];
    }
    float tv1 = 0.0f;
    if (EPI == 0 && TMODE == 1) tv1 = tvec[0];
    #pragma unroll
    for (int i = 0; i < 8; i++) {
        int row = bm + ty + i;
        float a[8];
        #pragma unroll
        for (int jp = 0; jp < 4; jp++) upk2(acc2[i][jp], a[2*jp], a[2*jp+1]);
        float v[8];
        if (EPI == 0) {
            float tval = (TMODE == 0) ? g_tcheb[row & 63] : tv1;
            #pragma unroll
            for (int j = 0; j < 8; j++) v[j] = tanhf(a[j] + bv[j] + tval);
        } else if (EPI == 1) {
            #pragma unroll
            for (int j = 0; j < 8; j++) v[j] = a[j] + bv[j];
        } else {
            #pragma unroll
            for (int j = 0; j < 8; j++) v[j] = a[j];
        }
        *(float4*)&C[(long)row*N + bn + tx]     = *(float4*)&v[0];
        *(float4*)&C[(long)row*N + bn + tx + 4] = *(float4*)&v[4];
    }
}

// ---------------- coefficients: B_fullT[(b,n), d] ---------------------------
__global__ void k_coef(int par) {
    if (g_done) return;
    int b = blockIdx.x, d = threadIdx.x;
    const float* Brow = g_B[par] + (long)(b*DIM + d) * NTAIL;
    float r0 = g_yf2[(b*DIM + d)*2 + 0];
    float r1 = g_yf2[(b*DIM + d)*2 + 1];
    float c[NC];
    #pragma unroll
    for (int j = 0; j < NTAIL; j++) {
        float bj = Brow[j];
        c[j+2] = bj;
        r0 -= bj * g_PD2[j*2+0];
        r1 -= bj * g_PD2[j*2+1];
    }
    c[0] = r0 * g_inv0[0] + r1 * g_inv0[2];
    c[1] = r0 * g_inv0[1] + r1 * g_inv0[3];
    #pragma unroll
    for (int n = 0; n < NC; n++)
        g_BT[(long)(b*NC + n)*DIM + d] = c[n];
}

// ---------------- fused expand+project, paired-p f32x2 ----------------------
// z for (p, p+1) packed: per-lane FMA chain over ascending n == R10's scalar
// chain. v = tanhf((z + bb) + t_p). hp chains per j: p ascending == R10.
__global__ void __launch_bounds__(256, 2) k_expandhp(const float* __restrict__ b1) {
    if (g_done) return;
    __shared__ __align__(8) float sPhi[NC][NP];  // p adjacent -> LDS.64 pairs
    __shared__ __align__(8) float sP[NP][32];    // PhibTQ padded to 32
    int tid = threadIdx.x, b = blockIdx.x, half = blockIdx.y;
    for (int i = tid; i < NC*NP; i += blockDim.x)
        ((float*)sPhi)[i] = g_Phi[i];
    for (int i = tid; i < NP*NTAIL; i += blockDim.x) {
        int p = i / NTAIL, n = i % NTAIL;
        sP[p][n] = g_PhibTQ[i];
    }
    if (tid < 2*NP) sP[tid >> 1][30 + (tid & 1)] = 0.0f;
    __syncthreads();

    int hh = half*256 + tid;
    unsigned long long wd[NC];
    #pragma unroll
    for (int n = 0; n < NC; n++) {
        float w = g_BW[(long)(b*NC + n)*HID + hh];
        wd[n] = pk2(w, w);
    }
    float bb = b1[hh];

    unsigned long long acc2[15];
    #pragma unroll
    for (int j = 0; j < 15; j++) acc2[j] = 0ull;

    for (int p = 0; p < NP; p += 2) {
        unsigned long long z2 = 0ull;
        #pragma unroll
        for (int n = 0; n < NC; n++)
            z2 = fma2(wd[n], *(const unsigned long long*)&sPhi[n][p], z2);
        float z0, z1;
        upk2(z2, z0, z1);
        float v0 = tanhf(z0 + bb + g_tcheb[p]);
        float v1 = tanhf(z1 + bb + g_tcheb[p+1]);
        unsigned long long v0d = pk2(v0, v0), v1d = pk2(v1, v1);
        const unsigned long long* P0 = (const unsigned long long*)&sP[p][0];
        const unsigned long long* P1 = (const unsigned long long*)&sP[p+1][0];
        #pragma unroll
        for (int j = 0; j < 15; j++) {
            acc2[j] = fma2(v0d, P0[j], acc2[j]);
            acc2[j] = fma2(v1d, P1[j], acc2[j]);
        }
    }
    #pragma unroll
    for (int j = 0; j < 15; j++) {
        float a0, a1;
        upk2(acc2[j], a0, a1);
        g_HP[(long)(b*NC + 2*j    )*HID + hh] = a0;
        g_HP[(long)(b*NC + 2*j + 1)*HID + hh] = a1;
    }
}

// ---------------- B_new from B1 + bias/M2 terms, delta partials -------------
__global__ void k_bnew(int par, const float* __restrict__ b2) {
    if (g_done) return;
    __shared__ float sM2[2][NTAIL];
    __shared__ float sS[NTAIL];
    int tid = threadIdx.x, b = blockIdx.x;
    if (tid < 2*NTAIL) ((float*)sM2)[tid] = g_M2[tid];
    if (tid < NTAIL) sS[tid] = g_Svec[tid];
    __syncthreads();
    int d = tid;
    float y0 = g_yf2[(b*DIM + d)*2 + 0];
    float y1 = g_yf2[(b*DIM + d)*2 + 1];
    float b2d = b2[d];
    const float* Bp = g_B[par] + (long)(b*DIM + d) * NTAIL;
    float* Bn = g_B[par ^ 1] + (long)(b*DIM + d) * NTAIL;
    float ss = 0.0f;
    #pragma unroll
    for (int n = 0; n < NTAIL; n++) {
        float val = g_B1[(long)(b*NC + n)*DIM + d] + b2d * sS[n]
                  - y0 * sM2[0][n] - y1 * sM2[1][n];
        Bn[n] = val;
        float df = val - Bp[n];
        ss += df * df;
    }
    #pragma unroll
    for (int o = 16; o > 0; o >>= 1) ss += __shfl_down_sync(0xffffffffu, ss, o);
    __shared__ float wsum[8];
    if ((tid & 31) == 0) wsum[tid >> 5] = ss;
    __syncthreads();
    if (tid == 0) {
        float t = 0.0f;
        #pragma unroll
        for (int w = 0; w < 8; w++) t += wsum[w];
        g_bsum[b] = t;
    }
}

__global__ void k_finalize(int par) {
    int tid = threadIdx.x;  // 256 threads
    __shared__ float sh[256];
    if (g_done) return;
    float s = g_bsum[tid] + g_bsum[tid + 256];
    sh[tid] = s;
    __syncthreads();
    for (int o = 128; o > 0; o >>= 1) {
        if (tid < o) sh[tid] += sh[tid + o];
        __syncthreads();
    }
    if (tid == 0) {
        float d = sqrtf(sh[0]);
        g_delta = d;
        g_fpar = par ^ 1;
        if (d < TOLF) g_done = 1;
    }
}

// ---------------- final trajectory ------------------------------------------
__global__ void k_traj(float* __restrict__ out_traj) {
    __shared__ float sPO[NC*TEV];
    int tid = threadIdx.x, b = blockIdx.x;
    for (int i = tid; i < NC*TEV; i += blockDim.x) sPO[i] = g_PhiOut[i];
    __syncthreads();
    int d = tid;
    const float* Brow = g_B[g_fpar] + (long)(b*DIM + d) * NTAIL;
    float r0 = g_yf2[(b*DIM + d)*2 + 0];
    float r1 = g_yf2[(b*DIM + d)*2 + 1];
    float c[NC];
    #pragma unroll
    for (int j = 0; j < NTAIL; j++) {
        float bj = Brow[j];
        c[j+2] = bj;
        r0 -= bj * g_PD2[j*2+0];
        r1 -= bj * g_PD2[j*2+1];
    }
    c[0] = r0 * g_inv0[0] + r1 * g_inv0[2];
    c[1] = r0 * g_inv0[1] + r1 * g_inv0[3];
    #pragma unroll
    for (int t = 0; t < TEV; t++) {
        float acc = 0.0f;
        #pragma unroll
        for (int n = 0; n < NC; n++) acc += c[n] * sPO[n*TEV + t];
        out_traj[((long)t*BATCH + b)*DIM + d] = acc;
    }
}

__global__ void k_misc(const float* __restrict__ t_eval, float* __restrict__ out, int tn) {
    int tid = threadIdx.x;
    if (tid < tn) out[tid] = t_eval[tid];
    if (tid == 31) out[DELTA_OFF] = g_delta;
}

// ---------------- launch ----------------------------------------------------
extern "C" void kernel_launch(void* const* d_in, const int* in_sizes, int n_in,
                              void* d_out, int out_size) {
    const float* y_init = (const float*)d_in[0];
    const float* t_eval = (const float*)d_in[1];
    const float* B_init = (const float*)d_in[2];
    const float* W1 = (const float*)d_in[3];
    const float* b1 = (const float*)d_in[4];
    const float* W2 = (const float*)d_in[5];
    const float* b2 = (const float*)d_in[6];
    float* out = (float*)d_out;
    int tn = in_sizes[1];

    float *pB0, *pBT, *pBW, *pHP, *pB1, *ph0, *pfi;
    cudaGetSymbolAddress((void**)&pB0, g_B);
    cudaGetSymbolAddress((void**)&pBT, g_BT);
    cudaGetSymbolAddress((void**)&pBW, g_BW);
    cudaGetSymbolAddress((void**)&pHP, g_HP);
    cudaGetSymbolAddress((void**)&pB1, g_B1);
    cudaGetSymbolAddress((void**)&ph0, g_h0);
    cudaGetSymbolAddress((void**)&pfi, g_fi);

    k_precompute<<<1, 256>>>(t_eval, tn);
    k_copy<<<2048, 256>>>(B_init, pB0, BSZ);

    // f_init = vf_point(t0, y_init)
    sgemm<0, 1, false><<<dim3(HID/128, BATCH/128), 256>>>(
        y_init, W1, ph0, b1, t_eval, BATCH, HID, DIM);
    sgemm<1, 0, false><<<dim3(DIM/128, BATCH/128), 256>>>(
        ph0, W2, pfi, b2, t_eval, BATCH, DIM, HID);
    k_yf2<<<(BATCH*DIM + 255)/256, 256>>>(y_init);

    for (int it = 0; it < MAXIT; it++) {
        int par = it & 1;
        k_coef<<<BATCH, 256>>>(par);
        sgemm<2, 0, true><<<dim3(HID/128, CROWS/128), 256>>>(
            pBT, W1, pBW, b1, t_eval, CROWS, HID, DIM);
        k_expandhp<<<dim3(BATCH, 2), 256>>>(b1);
        sgemm<2, 0, true><<<dim3(DIM/128, CROWS/128), 256>>>(
            pHP, W2, pB1, b2, t_eval, CROWS, DIM, HID);
        k_bnew<<<BATCH, 256>>>(par, b2);
        k_finalize<<<1, 256>>>(par);
    }

    k_traj<<<BATCH, 256>>>(out + TEV);
    k_misc<<<1, 32>>>(t_eval, out, tn);
    k_copyB<<<2048, 256>>>(out + B_OFF);
}

// round 15
// speedup vs baseline: 2.0098x; 1.0834x over previous
#include <cuda_runtime.h>
#include <math_constants.h>

#define BATCH 512
#define DIM   256
#define HID   512
#define NC    32      // NUM_COEFF
#define NTAIL 30      // NUM_COEFF - 2
#define NP    64      // Chebyshev points
#define TEV   16
#define MAXIT 10
#define TOLF  0.01f

#define MROWS (BATCH*NP)          // 32768
#define CROWS (BATCH*NC)          // 16384 coefficient-rows
#define BFSZ  (BATCH*NC*DIM)      // 4,194,304  (coef-major buffer)
#define BSZ   (BATCH*DIM*NTAIL)   // 3,932,160  (output tail size)
#define TRAJ_N (TEV*BATCH*DIM)    // 2,097,152
#define DELTA_OFF (TEV + TRAJ_N)  // 2,097,168
#define B_OFF (DELTA_OFF + 1)     // 2,097,169

// ---------------- scratch (device globals; no allocation allowed) ----------
__device__ float g_B[2][BFSZ];                // iterate, [b][n][d], rows 0,1 = head
__device__ float g_BW [CROWS*HID];            // BW      [(b,n), h]
__device__ float g_HP [CROWS*HID];            // HP      [(b,n), h]
__device__ float g_B1 [CROWS*DIM];            // B1      [(b,n), d]
__device__ float g_yf2[BATCH*DIM*2];
__device__ float g_h0[BATCH*HID];
__device__ float g_fi[BATCH*DIM];
__device__ float g_bsum[BATCH];

// small fp32 operators
__device__ float g_Phi[NC*NP];
__device__ float g_tcheb[NP];
__device__ float g_PD2[NTAIL*2];
__device__ float g_inv0[4];
__device__ float g_PhibTQ[NP*NTAIL];
__device__ float g_M2[2*NTAIL];
__device__ float g_Svec[NTAIL];
__device__ float g_PhiOut[NC*TEV];
__device__ float g_delta;
__device__ int   g_done;
__device__ int   g_fpar;

// double precompute workspace
__device__ double gd_tcheb[NP];
__device__ double gd_Dt[NP];
__device__ double gd_Phi[NC*NP];
__device__ double gd_DPhi[NC*NP];
__device__ double gd_C[2*NP];
__device__ double gd_Phib[NTAIL*NP];
__device__ double gd_G[NTAIL*60];       // augmented [G | I]
__device__ double gd_PhibTQ[NP*NTAIL];

#define DPI 3.14159265358979323846

// ---------------- f32x2 helpers (per-lane IEEE fma.rn) ----------------------
__device__ __forceinline__ unsigned long long pk2(float lo, float hi) {
    unsigned long long r;
    asm("mov.b64 %0, {%1, %2};" : "=l"(r) : "f"(lo), "f"(hi));
    return r;
}
__device__ __forceinline__ void upk2(unsigned long long v, float& lo, float& hi) {
    asm("mov.b64 {%0, %1}, %2;" : "=f"(lo), "=f"(hi) : "l"(v));
}
__device__ __forceinline__ unsigned long long fma2(unsigned long long a,
                                                   unsigned long long b,
                                                   unsigned long long c) {
    unsigned long long d;
    asm("fma.rn.f32x2 %0, %1, %2, %3;" : "=l"(d) : "l"(a), "l"(b), "l"(c));
    return d;
}

// ---------------- precompute spectral operators (1 block) ------------------
__global__ void k_precompute(const float* __restrict__ t_eval, int tn) {
    int tid = threadIdx.x;
    double t0 = (double)t_eval[0];
    double t1 = (double)t_eval[tn-1];
    double dtt = t1 - t0;
    double sg = (dtt > 0.0) ? 1.0 : ((dtt < 0.0) ? -1.0 : 0.0);
    double s = 2.0 / dtt;

    if (tid < NP) {
        double tc = -sg * cos(DPI * (double)tid / (double)NP);
        gd_tcheb[tid] = tc;
        g_tcheb[tid] = (float)tc;
        double Tm2 = 1.0, Tm1 = tc;
        gd_Phi[0*NP+tid] = 1.0;
        gd_Phi[1*NP+tid] = tc;
        #pragma unroll
        for (int n = 2; n < NC; n++) {
            double Tn = 2.0*tc*Tm1 - Tm2;
            gd_Phi[n*NP+tid] = Tn; Tm2 = Tm1; Tm1 = Tn;
        }
        double Um1 = 1.0, U = 2.0*tc;
        gd_DPhi[0*NP+tid] = 0.0;
        gd_DPhi[1*NP+tid] = s * 1.0 * Um1;
        gd_DPhi[2*NP+tid] = s * 2.0 * U;
        #pragma unroll
        for (int k = 3; k < NC; k++) {
            double Un = 2.0*tc*U - Um1;
            Um1 = U; U = Un;
            gd_DPhi[k*NP+tid] = s * (double)k * U;
        }
    }
    __syncthreads();
    if (tid < NP)
        gd_Dt[tid] = (tid < NP-1) ? (gd_tcheb[tid+1] - gd_tcheb[tid])
                                  : (1.0 - gd_tcheb[NP-1]);

    __shared__ double sinv0[4];
    if (tid == 0) {
        double a = gd_Phi[0], b = gd_DPhi[0];
        double c = gd_Phi[1*NP], d = gd_DPhi[1*NP];
        double det = a*d - b*c;
        sinv0[0] =  d/det; sinv0[1] = -b/det;
        sinv0[2] = -c/det; sinv0[3] =  a/det;
        g_inv0[0]=(float)sinv0[0]; g_inv0[1]=(float)sinv0[1];
        g_inv0[2]=(float)sinv0[2]; g_inv0[3]=(float)sinv0[3];
        g_done = 0;
        g_fpar = 0;
        g_delta = CUDART_INF_F;
    }
    __syncthreads();
    if (tid < 2*NP) {
        int k = tid / NP, p = tid % NP;
        gd_C[k*NP+p] = sinv0[k*2+0]*gd_DPhi[0*NP+p] + sinv0[k*2+1]*gd_DPhi[1*NP+p];
    }
    if (tid < NTAIL) {
        g_PD2[tid*2+0] = (float)gd_Phi [(tid+2)*NP + 0];
        g_PD2[tid*2+1] = (float)gd_DPhi[(tid+2)*NP + 0];
    }
    __syncthreads();
    for (int idx = tid; idx < NTAIL*NP; idx += blockDim.x) {
        int j = idx / NP, p = idx % NP;
        double pd0 = gd_Phi [(j+2)*NP + 0];
        double pd1 = gd_DPhi[(j+2)*NP + 0];
        gd_Phib[idx] = gd_DPhi[(j+2)*NP + p] - pd0*gd_C[0*NP+p] - pd1*gd_C[1*NP+p];
    }
    __syncthreads();
    for (int idx = tid; idx < NTAIL*NTAIL; idx += blockDim.x) {
        int i = idx / NTAIL, j = idx % NTAIL;
        double acc = 0.0;
        for (int p = 0; p < NP; p++)
            acc += gd_Phib[i*NP+p] * gd_Dt[p] * gd_Phib[j*NP+p];
        gd_G[i*60 + j] = acc;
        gd_G[i*60 + 30 + j] = (i == j) ? 1.0 : 0.0;
    }
    __syncthreads();
    __shared__ double fac[NTAIL];
    __shared__ double piv;
    for (int k = 0; k < NTAIL; k++) {
        if (tid == 0) piv = 1.0 / gd_G[k*60 + k];
        __syncthreads();
        for (int j = tid; j < 60; j += blockDim.x) gd_G[k*60 + j] *= piv;
        __syncthreads();
        if (tid < NTAIL && tid != k) fac[tid] = gd_G[tid*60 + k];
        __syncthreads();
        for (int idx = tid; idx < NTAIL*60; idx += blockDim.x) {
            int i = idx / 60, j = idx % 60;
            if (i != k) gd_G[idx] -= fac[i] * gd_G[k*60 + j];
        }
        __syncthreads();
    }
    for (int idx = tid; idx < NP*NTAIL; idx += blockDim.x) {
        int p = idx / NTAIL, n = idx % NTAIL;
        double acc = 0.0;
        for (int j = 0; j < NTAIL; j++)
            acc += gd_Phib[j*NP+p] * gd_G[j*60 + 30 + n];
        double v = gd_Dt[p] * acc;
        gd_PhibTQ[idx] = v;
        g_PhibTQ[idx] = (float)v;
    }
    __syncthreads();
    if (tid < 2*NTAIL) {
        int k = tid / NTAIL, n = tid % NTAIL;
        double acc = 0.0;
        for (int p = 0; p < NP; p++)
            acc += gd_C[k*NP+p] * gd_PhibTQ[p*NTAIL + n];
        g_M2[k*NTAIL+n] = (float)acc;
    }
    if (tid < NTAIL) {
        double acc = 0.0;
        for (int p = 0; p < NP; p++) acc += gd_PhibTQ[p*NTAIL + tid];
        g_Svec[tid] = (float)acc;
    }
    for (int idx = tid; idx < NC*NP; idx += blockDim.x)
        g_Phi[idx] = (float)gd_Phi[idx];
    if (tid < TEV) {
        double tt = -1.0 + 2.0*((double)t_eval[tid] - t0)/dtt;
        double Tm2 = 1.0, Tm1 = tt;
        g_PhiOut[0*TEV+tid] = 1.0f;
        g_PhiOut[1*TEV+tid] = (float)tt;
        #pragma unroll
        for (int n = 2; n < NC; n++) {
            double Tn = 2.0*tt*Tm1 - Tm2;
            g_PhiOut[n*TEV+tid] = (float)Tn; Tm2 = Tm1; Tm1 = Tn;
        }
    }
}

// ---------------- boundary transposes ---------------------------------------
// B_init [b,d,j] -> g_B[0] rows j+2 ([b][j+2][d])
__global__ void k_loadB(const float* __restrict__ Bi) {
    int b = blockIdx.x, d = threadIdx.x;
    const float* src = Bi + (long)(b*DIM + d) * NTAIL;
    float* dst = g_B[0] + (long)b*NC*DIM + d;
    #pragma unroll
    for (int j = 0; j < NTAIL; j++) dst[(j+2)*DIM] = src[j];
}

// g_B[g_fpar] rows 2..31 -> out [b,d,n]  (smem-tiled transpose)
__global__ void k_storeB(float* __restrict__ dst) {
    __shared__ float sm[NTAIL][DIM+1];
    int b = blockIdx.x, tid = threadIdx.x;
    const float* src = g_B[g_fpar] + (long)b*NC*DIM;
    for (int i = tid; i < NTAIL*DIM; i += 256) {
        int n = i / DIM, d = i % DIM;
        sm[n][d] = src[(n+2)*DIM + d];
    }
    __syncthreads();
    float* out = dst + (long)b*DIM*NTAIL;
    for (int i = tid; i < DIM*NTAIL; i += 256) {
        int d = i / NTAIL, n = i % NTAIL;
        out[i] = sm[n][d];
    }
}

// head rows 0,1 of g_B[0] from tail + yf2 (same chain as k_bnew's head part)
__global__ void k_init_head() {
    int b = blockIdx.x, d = threadIdx.x;
    const float* Br = g_B[0] + (long)b*NC*DIM + d;
    float r0 = g_yf2[(b*DIM + d)*2 + 0];
    float r1 = g_yf2[(b*DIM + d)*2 + 1];
    #pragma unroll
    for (int j = 0; j < NTAIL; j++) {
        float bj = Br[(j+2)*DIM];
        r0 -= bj * g_PD2[j*2+0];
        r1 -= bj * g_PD2[j*2+1];
    }
    g_B[0][(long)b*NC*DIM + 0*DIM + d] = r0 * g_inv0[0] + r1 * g_inv0[2];
    g_B[0][(long)b*NC*DIM + 1*DIM + d] = r0 * g_inv0[1] + r1 * g_inv0[3];
}

__global__ void k_yf2(const float* __restrict__ y_init) {
    int i = blockIdx.x * blockDim.x + threadIdx.x;
    if (i < BATCH*DIM) {
        g_yf2[2*i]   = y_init[i];
        g_yf2[2*i+1] = g_fi[i];
    }
}

// ---------------- SGEMM (TM*16)x128, K-chunk 16, f32x2 accumulators ---------
// TM = rows per thread (8 -> 128-row tile, 4 -> 64-row tile)
// EPI 0: C = tanhf(acc + bias + t)   EPI 1: C = acc + bias   EPI 2: C = acc
// TMODE 0: t = g_tcheb[row & 63]; TMODE 1: t = tvec[0]
template<int TM, int EPI, int TMODE, bool CHECK>
__launch_bounds__(256, 2)
__global__ void sgemm(const float* __restrict__ A, const float* __restrict__ B,
                      float* __restrict__ C, const float* __restrict__ bias,
                      const float* __restrict__ tvec, int M, int N, int K) {
    if (CHECK && g_done) return;
    __shared__ __align__(16) float As[2][16][TM*16+4];
    __shared__ __align__(16) float Bs[2][16][128];
    const int tid = threadIdx.x;
    const int bm = blockIdx.y * (TM*16), bn = blockIdx.x * 128;
    const int tx = (tid & 15) * 8, ty = (tid >> 4) * TM;
    const int NCH = K >> 4;

    unsigned long long acc2[TM][4];
    #pragma unroll
    for (int i = 0; i < TM; i++)
        #pragma unroll
        for (int jp = 0; jp < 4; jp++) acc2[i][jp] = 0ull;

    float4 ra[TM/4], rb[2];
    auto gload = [&](int c) {
        int k0 = c << 4;
        #pragma unroll
        for (int i = 0; i < TM/4; i++) {
            int idx = (i << 8) + tid;
            ra[i] = *(const float4*)(A + (long)(bm + (idx >> 2)) * K + k0 + ((idx & 3) << 2));
        }
        #pragma unroll
        for (int i = 0; i < 2; i++) {
            int idx = (i << 8) + tid;
            rb[i] = *(const float4*)(B + (long)(k0 + (idx >> 5)) * N + bn + ((idx & 31) << 2));
        }
    };
    auto sstore = [&](int s) {
        #pragma unroll
        for (int i = 0; i < TM/4; i++) {
            int idx = (i << 8) + tid;
            int row = idx >> 2, c4 = (idx & 3) << 2;
            As[s][c4+0][row] = ra[i].x;
            As[s][c4+1][row] = ra[i].y;
            As[s][c4+2][row] = ra[i].z;
            As[s][c4+3][row] = ra[i].w;
        }
        #pragma unroll
        for (int i = 0; i < 2; i++) {
            int idx = (i << 8) + tid;
            *(float4*)&Bs[s][idx >> 5][(idx & 31) << 2] = rb[i];
        }
    };

    gload(0);
    sstore(0);
    if (NCH > 1) gload(1);
    __syncthreads();

    for (int c = 0; c < NCH; c++) {
        int s = c & 1;
        if (c + 1 < NCH) sstore(s ^ 1);
        if (c + 2 < NCH) gload(c + 2);
        #pragma unroll
        for (int k = 0; k < 16; k++) {
            float ar[TM];
            #pragma unroll
            for (int q = 0; q < TM/4; q++) {
                float4 av = *(const float4*)&As[s][k][ty + q*4];
                ar[q*4+0] = av.x; ar[q*4+1] = av.y;
                ar[q*4+2] = av.z; ar[q*4+3] = av.w;
            }
            ulonglong2 bb0 = *(const ulonglong2*)&Bs[s][k][tx];
            ulonglong2 bb1 = *(const ulonglong2*)&Bs[s][k][tx+4];
            unsigned long long b2v[4] = {bb0.x, bb0.y, bb1.x, bb1.y};
            #pragma unroll
            for (int i = 0; i < TM; i++) {
                unsigned long long ad = pk2(ar[i], ar[i]);
                #pragma unroll
                for (int jp = 0; jp < 4; jp++)
                    acc2[i][jp] = fma2(ad, b2v[jp], acc2[i][jp]);
            }
        }
        __syncthreads();
    }

    float bv[8];
    if (EPI != 2) {
        *(float4*)&bv[0] = *(const float4*)&bias[bn + tx];
        *(float4*)&bv[4] = *(const float4*)&bias[bn + tx + 4];
    }
    float tv1 = 0.0f;
    if (EPI == 0 && TMODE == 1) tv1 = tvec[0];
    #pragma unroll
    for (int i = 0; i < TM; i++) {
        int row = bm + ty + i;
        float a[8];
        #pragma unroll
        for (int jp = 0; jp < 4; jp++) upk2(acc2[i][jp], a[2*jp], a[2*jp+1]);
        float v[8];
        if (EPI == 0) {
            float tval = (TMODE == 0) ? g_tcheb[row & 63] : tv1;
            #pragma unroll
            for (int j = 0; j < 8; j++) v[j] = tanhf(a[j] + bv[j] + tval);
        } else if (EPI == 1) {
            #pragma unroll
            for (int j = 0; j < 8; j++) v[j] = a[j] + bv[j];
        } else {
            #pragma unroll
            for (int j = 0; j < 8; j++) v[j] = a[j];
        }
        *(float4*)&C[(long)row*N + bn + tx]     = *(float4*)&v[0];
        *(float4*)&C[(long)row*N + bn + tx + 4] = *(float4*)&v[4];
    }
}

// ---------------- fused expand+project, paired-p f32x2 ----------------------
__global__ void __launch_bounds__(256, 2) k_expandhp(const float* __restrict__ b1) {
    if (g_done) return;
    __shared__ __align__(8) float sPhi[NC][NP];
    __shared__ __align__(8) float sP[NP][32];
    int tid = threadIdx.x, b = blockIdx.x, half = blockIdx.y;
    for (int i = tid; i < NC*NP; i += blockDim.x)
        ((float*)sPhi)[i] = g_Phi[i];
    for (int i = tid; i < NP*NTAIL; i += blockDim.x) {
        int p = i / NTAIL, n = i % NTAIL;
        sP[p][n] = g_PhibTQ[i];
    }
    if (tid < 2*NP) sP[tid >> 1][30 + (tid & 1)] = 0.0f;
    __syncthreads();

    int hh = half*256 + tid;
    unsigned long long wd[NC];
    #pragma unroll
    for (int n = 0; n < NC; n++) {
        float w = g_BW[(long)(b*NC + n)*HID + hh];
        wd[n] = pk2(w, w);
    }
    float bb = b1[hh];

    unsigned long long acc2[15];
    #pragma unroll
    for (int j = 0; j < 15; j++) acc2[j] = 0ull;

    for (int p = 0; p < NP; p += 2) {
        unsigned long long z2 = 0ull;
        #pragma unroll
        for (int n = 0; n < NC; n++)
            z2 = fma2(wd[n], *(const unsigned long long*)&sPhi[n][p], z2);
        float z0, z1;
        upk2(z2, z0, z1);
        float v0 = tanhf(z0 + bb + g_tcheb[p]);
        float v1 = tanhf(z1 + bb + g_tcheb[p+1]);
        unsigned long long v0d = pk2(v0, v0), v1d = pk2(v1, v1);
        const unsigned long long* P0 = (const unsigned long long*)&sP[p][0];
        const unsigned long long* P1 = (const unsigned long long*)&sP[p+1][0];
        #pragma unroll
        for (int j = 0; j < 15; j++) {
            acc2[j] = fma2(v0d, P0[j], acc2[j]);
            acc2[j] = fma2(v1d, P1[j], acc2[j]);
        }
    }
    #pragma unroll
    for (int j = 0; j < 15; j++) {
        float a0, a1;
        upk2(acc2[j], a0, a1);
        g_HP[(long)(b*NC + 2*j    )*HID + hh] = a0;
        g_HP[(long)(b*NC + 2*j + 1)*HID + hh] = a1;
    }
}

// ---------------- B_new (tail rows 2..31 + head rows 0,1) + delta -----------
__global__ void k_bnew(int par, const float* __restrict__ b2) {
    if (g_done) return;
    __shared__ float sM2[2][NTAIL];
    __shared__ float sS[NTAIL];
    int tid = threadIdx.x, b = blockIdx.x;
    if (tid < 2*NTAIL) ((float*)sM2)[tid] = g_M2[tid];
    if (tid < NTAIL) sS[tid] = g_Svec[tid];
    __syncthreads();
    int d = tid;
    float y0 = g_yf2[(b*DIM + d)*2 + 0];
    float y1 = g_yf2[(b*DIM + d)*2 + 1];
    float b2d = b2[d];
    const float* Bp = g_B[par]     + (long)b*NC*DIM + d;
    float*       Bn = g_B[par ^ 1] + (long)b*NC*DIM + d;
    float r0 = y0, r1 = y1;
    float ss = 0.0f;
    #pragma unroll
    for (int n = 0; n < NTAIL; n++) {
        float val = g_B1[(long)(b*NC + n)*DIM + d] + b2d * sS[n]
                  - y0 * sM2[0][n] - y1 * sM2[1][n];
        Bn[(n+2)*DIM] = val;
        float df = val - Bp[(n+2)*DIM];
        ss += df * df;
        r0 -= val * g_PD2[n*2+0];
        r1 -= val * g_PD2[n*2+1];
    }
    Bn[0*DIM] = r0 * g_inv0[0] + r1 * g_inv0[2];
    Bn[1*DIM] = r0 * g_inv0[1] + r1 * g_inv0[3];
    #pragma unroll
    for (int o = 16; o > 0; o >>= 1) ss += __shfl_down_sync(0xffffffffu, ss, o);
    __shared__ float wsum[8];
    if ((tid & 31) == 0) wsum[tid >> 5] = ss;
    __syncthreads();
    if (tid == 0) {
        float t = 0.0f;
        #pragma unroll
        for (int w = 0; w < 8; w++) t += wsum[w];
        g_bsum[b] = t;
    }
}

__global__ void k_finalize(int par) {
    int tid = threadIdx.x;  // 256 threads
    __shared__ float sh[256];
    if (g_done) return;
    float s = g_bsum[tid] + g_bsum[tid + 256];
    sh[tid] = s;
    __syncthreads();
    for (int o = 128; o > 0; o >>= 1) {
        if (tid < o) sh[tid] += sh[tid + o];
        __syncthreads();
    }
    if (tid == 0) {
        float d = sqrtf(sh[0]);
        g_delta = d;
        g_fpar = par ^ 1;
        if (d < TOLF) g_done = 1;
    }
}

// ---------------- final trajectory (reads head rows directly) ---------------
__global__ void k_traj(float* __restrict__ out_traj) {
    __shared__ float sPO[NC*TEV];
    int tid = threadIdx.x, b = blockIdx.x;
    for (int i = tid; i < NC*TEV; i += blockDim.x) sPO[i] = g_PhiOut[i];
    __syncthreads();
    int d = tid;
    const float* Br = g_B[g_fpar] + (long)b*NC*DIM + d;
    float c[NC];
    #pragma unroll
    for (int n = 0; n < NC; n++) c[n] = Br[n*DIM];
    #pragma unroll
    for (int t = 0; t < TEV; t++) {
        float acc = 0.0f;
        #pragma unroll
        for (int n = 0; n < NC; n++) acc += c[n] * sPO[n*TEV + t];
        out_traj[((long)t*BATCH + b)*DIM + d] = acc;
    }
}

__global__ void k_misc(const float* __restrict__ t_eval, float* __restrict__ out, int tn) {
    int tid = threadIdx.x;
    if (tid < tn) out[tid] = t_eval[tid];
    if (tid == 31) out[DELTA_OFF] = g_delta;
}

// ---------------- launch ----------------------------------------------------
extern "C" void kernel_launch(void* const* d_in, const int* in_sizes, int n_in,
                              void* d_out, int out_size) {
    const float* y_init = (const float*)d_in[0];
    const float* t_eval = (const float*)d_in[1];
    const float* B_init = (const float*)d_in[2];
    const float* W1 = (const float*)d_in[3];
    const float* b1 = (const float*)d_in[4];
    const float* W2 = (const float*)d_in[5];
    const float* b2 = (const float*)d_in[6];
    float* out = (float*)d_out;
    int tn = in_sizes[1];

    float *pB0, *pBW, *pHP, *pB1, *ph0, *pfi;
    cudaGetSymbolAddress((void**)&pB0, g_B);
    cudaGetSymbolAddress((void**)&pBW, g_BW);
    cudaGetSymbolAddress((void**)&pHP, g_HP);
    cudaGetSymbolAddress((void**)&pB1, g_B1);
    cudaGetSymbolAddress((void**)&ph0, g_h0);
    cudaGetSymbolAddress((void**)&pfi, g_fi);

    k_precompute<<<1, 256>>>(t_eval, tn);
    k_loadB<<<BATCH, 256>>>(B_init);

    // f_init = vf_point(t0, y_init)  (64-row tiles for better small-M spread)
    sgemm<4, 0, 1, false><<<dim3(HID/128, BATCH/64), 256>>>(
        y_init, W1, ph0, b1, t_eval, BATCH, HID, DIM);
    sgemm<4, 1, 0, false><<<dim3(DIM/128, BATCH/64), 256>>>(
        ph0, W2, pfi, b2, t_eval, BATCH, DIM, HID);
    k_yf2<<<(BATCH*DIM + 255)/256, 256>>>(y_init);
    k_init_head<<<BATCH, 256>>>();

    for (int it = 0; it < MAXIT; it++) {
        int par = it & 1;
        float* pBcur = pB0 + (long)par * BFSZ;
        sgemm<8, 2, 0, true><<<dim3(HID/128, CROWS/128), 256>>>(
            pBcur, W1, pBW, b1, t_eval, CROWS, HID, DIM);
        k_expandhp<<<dim3(BATCH, 2), 256>>>(b1);
        sgemm<8, 2, 0, true><<<dim3(DIM/128, CROWS/128), 256>>>(
            pHP, W2, pB1, b2, t_eval, CROWS, DIM, HID);
        k_bnew<<<BATCH, 256>>>(par, b2);
        k_finalize<<<1, 256>>>(par);
    }

    k_traj<<<BATCH, 256>>>(out + TEV);
    k_misc<<<1, 32>>>(t_eval, out, tn);
    k_storeB<<<BATCH, 256>>>(out + B_OFF);
}